// round 4
// baseline (speedup 1.0000x reference)
#include <cuda_runtime.h>
#include <cuda_bf16.h>
#include <stdint.h>

#define BATCH 4096
#define NCLS  50257
#define EPSV  1e-12f

// Per-row loss scratch (no device allocation allowed -> __device__ global)
__device__ float g_row_loss[BATCH];

__device__ __forceinline__ float stable_s(float x) {
    // x >= 0 ? x + 1 : 1/(1-x)
    float p = x + 1.0f;
    float n = 1.0f - x;
    float r = __fdividef(1.0f, n);   // MUFU.RCP + FMUL (approx; ~1e-6 rel err)
    return (x >= 0.0f) ? p : r;
}

__device__ __forceinline__ float s4(float4 v) {
    return (stable_s(v.x) + stable_s(v.y)) + (stable_s(v.z) + stable_s(v.w));
}

__device__ __forceinline__ float block_reduce_sum(float v) {
    __shared__ float warp_sums[32];
    int lane = threadIdx.x & 31;
    int wid  = threadIdx.x >> 5;
    #pragma unroll
    for (int off = 16; off > 0; off >>= 1)
        v += __shfl_xor_sync(0xffffffffu, v, off);
    if (lane == 0) warp_sums[wid] = v;
    __syncthreads();
    int nwarps = (blockDim.x + 31) >> 5;
    v = (threadIdx.x < nwarps) ? warp_sums[threadIdx.x] : 0.0f;
    if (wid == 0) {
        #pragma unroll
        for (int off = 16; off > 0; off >>= 1)
            v += __shfl_xor_sync(0xffffffffu, v, off);
    }
    return v;  // valid in thread 0
}

__global__ void __launch_bounds__(256)
stablemax_row_kernel(const float* __restrict__ logits,
                     const int* __restrict__ targets) {
    const int row = blockIdx.x;
    const float* __restrict__ rp = logits + (size_t)row * NCLS;
    const int stride = blockDim.x;   // 256

    float acc0 = 0.0f, acc1 = 0.0f, acc2 = 0.0f, acc3 = 0.0f;

    // Scalar prefix until 16B alignment (row base is only 4B aligned: NCLS odd)
    int prefix = (int)(((16u - ((uintptr_t)rp & 15u)) & 15u) >> 2);
    if (prefix > NCLS) prefix = NCLS;
    for (int j = threadIdx.x; j < prefix; j += stride)
        acc0 += stable_s(rp[j]);

    // Vectorized main body, 4x unrolled: 4 independent LDG.128 in flight,
    // 4 independent accumulator chains.
    const int n4 = (NCLS - prefix) >> 2;
    const float4* __restrict__ rp4 = (const float4*)(rp + prefix);
    int j = threadIdx.x;
    for (; j + 3 * stride < n4; j += 4 * stride) {
        float4 v0 = rp4[j];
        float4 v1 = rp4[j + stride];
        float4 v2 = rp4[j + 2 * stride];
        float4 v3 = rp4[j + 3 * stride];
        acc0 += s4(v0);
        acc1 += s4(v1);
        acc2 += s4(v2);
        acc3 += s4(v3);
    }
    for (; j < n4; j += stride)
        acc0 += s4(rp4[j]);

    // Scalar tail (at most 3 elements)
    for (int t = prefix + (n4 << 2) + threadIdx.x; t < NCLS; t += stride)
        acc1 += stable_s(rp[t]);

    float denom = block_reduce_sum((acc0 + acc1) + (acc2 + acc3));

    if (threadIdx.x == 0) {
        int t = targets[row];
        // Defensive clamp: a bad dtype assumption should produce a wrong
        // value (diagnosable), not an illegal access (opaque).
        t = min(max(t, 0), NCLS - 1);
        float st = stable_s(rp[t]);
        denom = fmaxf(denom, EPSV);
        float pt = fmaxf(__fdividef(st, denom), EPSV);
        g_row_loss[row] = -__logf(pt);
    }
}

__global__ void __launch_bounds__(1024)
stablemax_mean_kernel(float* __restrict__ out) {
    // BATCH = 4096 = 1024 threads * 4 -> one float4 per thread
    const float4* __restrict__ rl4 = (const float4*)g_row_loss;
    float4 v = rl4[threadIdx.x];
    float acc = (v.x + v.y) + (v.z + v.w);
    float total = block_reduce_sum(acc);
    if (threadIdx.x == 0)
        out[0] = total * (1.0f / (float)BATCH);
}

extern "C" void kernel_launch(void* const* d_in, const int* in_sizes, int n_in,
                              void* d_out, int out_size) {
    const float* logits  = (const float*)d_in[0];
    const int*   targets = (const int*)d_in[1];
    float*       out     = (float*)d_out;
    (void)in_sizes; (void)n_in; (void)out_size;

    stablemax_row_kernel<<<BATCH, 256>>>(logits, targets);
    stablemax_mean_kernel<<<1, 1024>>>(out);
}

// round 8
// speedup vs baseline: 1.0031x; 1.0031x over previous
#include <cuda_runtime.h>
#include <cuda_bf16.h>
#include <stdint.h>

#define BATCH 4096
#define NCLS  50257
#define EPSV  1e-12f

// Scratch + completion counter (no device allocation allowed -> __device__ globals)
__device__ float g_row_loss[BATCH];
__device__ unsigned int g_done = 0;

__device__ __forceinline__ float stable_s(float x) {
    // x >= 0 ? x + 1 : 1/(1-x)
    float p = x + 1.0f;
    float n = 1.0f - x;
    float r = __fdividef(1.0f, n);   // MUFU.RCP path (~1e-6 rel err)
    return (x >= 0.0f) ? p : r;
}

__device__ __forceinline__ float s4(float4 v) {
    return (stable_s(v.x) + stable_s(v.y)) + (stable_s(v.z) + stable_s(v.w));
}

// Re-entrant block reduction (leading barrier protects smem reuse across calls).
__device__ __forceinline__ float block_reduce_sum(float v) {
    __shared__ float warp_sums[8];
    int lane = threadIdx.x & 31;
    int wid  = threadIdx.x >> 5;
    __syncthreads();
    #pragma unroll
    for (int off = 16; off > 0; off >>= 1)
        v += __shfl_xor_sync(0xffffffffu, v, off);
    if (lane == 0) warp_sums[wid] = v;
    __syncthreads();
    v = (threadIdx.x < 8) ? warp_sums[threadIdx.x] : 0.0f;
    if (wid == 0) {
        #pragma unroll
        for (int off = 4; off > 0; off >>= 1)
            v += __shfl_xor_sync(0xffffffffu, v, off);
    }
    return v;  // valid in thread 0
}

__global__ void __launch_bounds__(256)
stablemax_fused_kernel(const float* __restrict__ logits,
                       const int* __restrict__ targets,
                       float* __restrict__ out) {
    const int row = blockIdx.x;
    const float* __restrict__ rp = logits + (size_t)row * NCLS;
    const int stride = 256;

    // Hoist the target index load: issue it before the streaming loop so the
    // DRAM latency overlaps with the main body instead of serializing at the end.
    int tgt = 0;
    if (threadIdx.x == 0) {
        tgt = __ldg(&targets[row]);
        tgt = min(max(tgt, 0), NCLS - 1);   // fail-soft on dtype surprises
    }

    float acc0 = 0.0f, acc1 = 0.0f, acc2 = 0.0f, acc3 = 0.0f;

    // Scalar prefix until 16B alignment (row base only 4B aligned: NCLS odd)
    int prefix = (int)(((16u - ((uintptr_t)rp & 15u)) & 15u) >> 2);
    if (prefix > NCLS) prefix = NCLS;
    for (int j = threadIdx.x; j < prefix; j += stride)
        acc0 += stable_s(rp[j]);

    // Vectorized main body, 4x unrolled: 4 independent LDG.128 in flight,
    // 4 independent accumulator chains.
    const int n4 = (NCLS - prefix) >> 2;
    const float4* __restrict__ rp4 = (const float4*)(rp + prefix);
    int j = threadIdx.x;
    for (; j + 3 * stride < n4; j += 4 * stride) {
        float4 v0 = rp4[j];
        float4 v1 = rp4[j + stride];
        float4 v2 = rp4[j + 2 * stride];
        float4 v3 = rp4[j + 3 * stride];
        acc0 += s4(v0);
        acc1 += s4(v1);
        acc2 += s4(v2);
        acc3 += s4(v3);
    }
    for (; j < n4; j += stride)
        acc0 += s4(rp4[j]);

    // Scalar tail (at most 3 elements)
    for (int t = prefix + (n4 << 2) + threadIdx.x; t < NCLS; t += stride)
        acc1 += stable_s(rp[t]);

    // Issue the dependent target-logit load before the block reduction so its
    // latency hides under the two barriers + shuffle tree.
    float st = 0.0f;
    if (threadIdx.x == 0)
        st = stable_s(__ldg(&rp[tgt]));

    float denom = block_reduce_sum((acc0 + acc1) + (acc2 + acc3));

    __shared__ bool is_last;
    if (threadIdx.x == 0) {
        denom = fmaxf(denom, EPSV);
        float pt = fmaxf(__fdividef(st, denom), EPSV);
        g_row_loss[row] = -__logf(pt);
        __threadfence();                         // publish row loss (release)
        unsigned int done = atomicAdd(&g_done, 1u);
        is_last = (done == (unsigned int)(BATCH - 1));
    }
    __syncthreads();

    if (is_last) {
        // Deterministic mean: fixed-order tree over g_row_loss.
        // 4096 floats = 1024 float4; 256 threads -> 4 float4 each, fixed indices.
        const float4* __restrict__ rl4 = (const float4*)g_row_loss;
        float acc = 0.0f;
        #pragma unroll
        for (int k = 0; k < 4; k++) {
            float4 v = __ldcg(&rl4[threadIdx.x + k * 256]);  // L2-coherent read
            acc += (v.x + v.y) + (v.z + v.w);
        }
        float total = block_reduce_sum(acc);
        if (threadIdx.x == 0) {
            out[0] = total * (1.0f / (float)BATCH);
            g_done = 0;                          // reset for next graph replay
        }
    }
}

extern "C" void kernel_launch(void* const* d_in, const int* in_sizes, int n_in,
                              void* d_out, int out_size) {
    const float* logits  = (const float*)d_in[0];
    const int*   targets = (const int*)d_in[1];
    float*       out     = (float*)d_out;
    (void)in_sizes; (void)n_in; (void)out_size;

    stablemax_fused_kernel<<<BATCH, 256>>>(logits, targets, out);
}

// round 9
// speedup vs baseline: 1.0819x; 1.0786x over previous
#include <cuda_runtime.h>
#include <cuda_bf16.h>
#include <stdint.h>

#define BATCH 4096
#define NCLS  50257
#define EPSV  1e-12f

// Scratch + completion counter (no device allocation allowed -> __device__ globals)
__device__ float g_row_loss[BATCH];
__device__ unsigned int g_done = 0;

__device__ __forceinline__ float stable_s(float x) {
    // x >= 0 ? x + 1 : 1/(1-x)
    float p = x + 1.0f;
    float n = 1.0f - x;
    float r = __fdividef(1.0f, n);   // MUFU.RCP path (~1e-6 rel err)
    return (x >= 0.0f) ? p : r;
}

__device__ __forceinline__ float s4(float4 v) {
    return (stable_s(v.x) + stable_s(v.y)) + (stable_s(v.z) + stable_s(v.w));
}

// Re-entrant block reduction (leading barrier protects smem reuse across calls).
__device__ __forceinline__ float block_reduce_sum(float v) {
    __shared__ float warp_sums[8];
    int lane = threadIdx.x & 31;
    int wid  = threadIdx.x >> 5;
    __syncthreads();
    #pragma unroll
    for (int off = 16; off > 0; off >>= 1)
        v += __shfl_xor_sync(0xffffffffu, v, off);
    if (lane == 0) warp_sums[wid] = v;
    __syncthreads();
    v = (threadIdx.x < 8) ? warp_sums[threadIdx.x] : 0.0f;
    if (wid == 0) {
        #pragma unroll
        for (int off = 4; off > 0; off >>= 1)
            v += __shfl_xor_sync(0xffffffffu, v, off);
    }
    return v;  // valid in thread 0
}

__global__ void __launch_bounds__(256, 4)
stablemax_fused_kernel(const float* __restrict__ logits,
                       const int* __restrict__ targets,
                       float* __restrict__ out) {
    const int row = blockIdx.x;
    const float* __restrict__ rp = logits + (size_t)row * NCLS;
    const int stride = 256;

    // Hoist the target index load so its DRAM latency overlaps the main body.
    int tgt = 0;
    if (threadIdx.x == 0) {
        tgt = __ldg(&targets[row]);
        tgt = min(max(tgt, 0), NCLS - 1);   // fail-soft on dtype surprises
    }

    float acc0 = 0.f, acc1 = 0.f, acc2 = 0.f, acc3 = 0.f,
          acc4 = 0.f, acc5 = 0.f, acc6 = 0.f, acc7 = 0.f;

    // Scalar prefix until 16B alignment (row base only 4B aligned: NCLS odd)
    int prefix = (int)(((16u - ((uintptr_t)rp & 15u)) & 15u) >> 2);
    if (prefix > NCLS) prefix = NCLS;
    for (int j = threadIdx.x; j < prefix; j += stride)
        acc0 += stable_s(rp[j]);

    // Vectorized main body, 8x unrolled: 8 independent LDG.128 in flight
    // (doubles per-SM outstanding bytes vs 4x — we measured DRAM=76.5% there,
    // latency-limited), 8 independent accumulator chains.
    const int n4 = (NCLS - prefix) >> 2;
    const float4* __restrict__ rp4 = (const float4*)(rp + prefix);
    int j = threadIdx.x;
    for (; j + 7 * stride < n4; j += 8 * stride) {
        float4 v0 = rp4[j];
        float4 v1 = rp4[j +     stride];
        float4 v2 = rp4[j + 2 * stride];
        float4 v3 = rp4[j + 3 * stride];
        float4 v4 = rp4[j + 4 * stride];
        float4 v5 = rp4[j + 5 * stride];
        float4 v6 = rp4[j + 6 * stride];
        float4 v7 = rp4[j + 7 * stride];
        acc0 += s4(v0);
        acc1 += s4(v1);
        acc2 += s4(v2);
        acc3 += s4(v3);
        acc4 += s4(v4);
        acc5 += s4(v5);
        acc6 += s4(v6);
        acc7 += s4(v7);
    }
    for (; j < n4; j += stride)
        acc0 += s4(rp4[j]);

    // Scalar tail (at most 3 elements)
    for (int t = prefix + (n4 << 2) + threadIdx.x; t < NCLS; t += stride)
        acc1 += stable_s(rp[t]);

    // Dependent target-logit load issued before the block reduction so its
    // latency hides under the barriers + shuffle tree.
    float st = 0.0f;
    if (threadIdx.x == 0)
        st = stable_s(__ldg(&rp[tgt]));

    float denom = block_reduce_sum(((acc0 + acc1) + (acc2 + acc3)) +
                                   ((acc4 + acc5) + (acc6 + acc7)));

    __shared__ bool is_last;
    if (threadIdx.x == 0) {
        denom = fmaxf(denom, EPSV);
        float pt = fmaxf(__fdividef(st, denom), EPSV);
        g_row_loss[row] = -__logf(pt);
        __threadfence();                         // publish row loss (release)
        unsigned int done = atomicAdd(&g_done, 1u);
        is_last = (done == (unsigned int)(BATCH - 1));
    }
    __syncthreads();

    if (is_last) {
        // Deterministic mean: fixed-order tree over g_row_loss.
        // 4096 floats = 1024 float4; 256 threads -> 4 float4 each, fixed indices.
        const float4* __restrict__ rl4 = (const float4*)g_row_loss;
        float acc = 0.0f;
        #pragma unroll
        for (int k = 0; k < 4; k++) {
            float4 v = __ldcg(&rl4[threadIdx.x + k * 256]);  // L2-coherent read
            acc += (v.x + v.y) + (v.z + v.w);
        }
        float total = block_reduce_sum(acc);
        if (threadIdx.x == 0) {
            out[0] = total * (1.0f / (float)BATCH);
            g_done = 0;                          // reset for next graph replay
        }
    }
}

extern "C" void kernel_launch(void* const* d_in, const int* in_sizes, int n_in,
                              void* d_out, int out_size) {
    const float* logits  = (const float*)d_in[0];
    const int*   targets = (const int*)d_in[1];
    float*       out     = (float*)d_out;
    (void)in_sizes; (void)n_in; (void)out_size;

    stablemax_fused_kernel<<<BATCH, 256>>>(logits, targets, out);
}